// round 16
// baseline (speedup 1.0000x reference)
#include <cuda_runtime.h>
#include <cuda_bf16.h>
#include <math.h>
#include <stdint.h>

#define TOK   100352          // B*H*W = 32*56*56
#define CC    192
#define NHEAD 6
#define EPSLN 1e-5f

typedef __nv_bfloat16 bf16;

// pack two floats into one bf16x2 register word (lo = first, hi = second)
__device__ __forceinline__ uint32_t pack_bf2(float a, float b) {
    __nv_bfloat162 h = __floats2bfloat162_rn(a, b);
    __nv_bfloat162_raw r = *reinterpret_cast<__nv_bfloat162_raw*>(&h);
    return (uint32_t)r.x | ((uint32_t)r.y << 16);
}

struct __align__(8) bf164 { __nv_bfloat162 a, b; };

// ---------------- scratch ---------------------------------------------------
__device__ bf16  g_xw [(size_t)TOK * CC];
__device__ bf16  g_qkv[(size_t)TOK * 576];
__device__ bf16  g_att[(size_t)TOK * CC];
__device__ float g_y  [(size_t)TOK * CC];
__device__ bf16  g_xn2[(size_t)TOK * CC];
__device__ bf16  g_h1 [(size_t)TOK * 768];
__device__ bf16  g_wq [192 * 576];
__device__ bf16  g_wp [192 * 192];
__device__ bf16  g_w1 [192 * 768];
__device__ bf16  g_w2 [768 * 192];
__device__ bf16  g_bias[24 * 49 * 64];   // [cls*6+head][n][m] rpb+mask (bf16)

// window-token index -> natural token index (cyclic shift +3)
__device__ __forceinline__ int win_to_nat(int o) {
    int b    = o / 3136;
    int r    = o - b * 3136;
    int w    = r / 49;
    int cell = r - w * 49;
    int wh = w >> 3, ww = w & 7;
    int i = cell / 7, j = cell - 7 * (cell / 7);
    int h  = wh * 7 + i + 3; if (h  >= 56) h  -= 56;
    int w2 = ww * 7 + j + 3; if (w2 >= 56) w2 -= 56;
    return b * 3136 + h * 56 + w2;
}

__device__ __forceinline__ void cp16(uint32_t dst, const void* src) {
    asm volatile("cp.async.cg.shared.global [%0], [%1], 16;" :: "r"(dst), "l"(src));
}

// ---------------- fused weight f32 -> bf16 ----------------------------------
__global__ void cvt_all_kernel(const float* __restrict__ w0, const float* __restrict__ w1,
                               const float* __restrict__ w2, const float* __restrict__ w3,
                               bf16* o0, bf16* o1, bf16* o2, bf16* o3) {
    int i = blockIdx.x * 256 + threadIdx.x;       // 110592 quads total
    const float* src; bf16* dst; int off;
    if (i < 27648)      { src = w0; dst = o0; off = i; }
    else if (i < 36864) { src = w1; dst = o1; off = i - 27648; }
    else if (i < 73728) { src = w2; dst = o2; off = i - 36864; }
    else                { src = w3; dst = o3; off = i - 73728; }
    float4 v = ((const float4*)src)[off];
    __nv_bfloat162* p = (__nv_bfloat162*)dst;
    p[2 * off + 0] = __floats2bfloat162_rn(v.x, v.y);
    p[2 * off + 1] = __floats2bfloat162_rn(v.z, v.w);
}

// ---------------- bias table: rpb gather + analytic shift mask (bf16) -------
__global__ void bias_kernel(const float* __restrict__ rpb, bf16* __restrict__ btab) {
    int cls  = blockIdx.x / 6;
    int head = blockIdx.x - cls * 6;
    int clsH = cls >> 1, clsW = cls & 1;
    for (int idx = threadIdx.x; idx < 49 * 64; idx += 256) {
        int n = idx >> 6, m = idx & 63;
        float v;
        if (m < 49) {
            int i1 = n / 7, j1 = n - 7 * i1;
            int i2 = m / 7, j2 = m - 7 * i2;
            v = rpb[((i1 - i2 + 6) * 13 + (j1 - j2 + 6)) * NHEAD + head];
            int ra = clsH ? (i1 < 4 ? 1 : 2) : 0;
            int rb = clsW ? (j1 < 4 ? 1 : 2) : 0;
            int ca = clsH ? (i2 < 4 ? 1 : 2) : 0;
            int cb = clsW ? (j2 < 4 ? 1 : 2) : 0;
            if (3 * ra + rb != 3 * ca + cb) v -= 100.f;
        } else v = -1e30f;
        btab[(size_t)blockIdx.x * 49 * 64 + idx] = __float2bfloat16(v);
    }
}

// ---------------- LayerNorm (one warp per token), float4 loads --------------
template<bool GATHER>
__global__ void ln_kernel(const float* __restrict__ x,
                          const float* __restrict__ gam,
                          const float* __restrict__ bet,
                          bf16* __restrict__ out) {
    int token = blockIdx.x * 8 + (threadIdx.x >> 5);
    int lane  = threadIdx.x & 31;
    int src   = GATHER ? win_to_nat(token) : token;
    const float4* xp4 = (const float4*)(x + (size_t)src * CC);   // 48 float4
    const bool hi = lane < 16;

    float4 a = xp4[lane];
    float4 b = make_float4(0.f, 0.f, 0.f, 0.f);
    if (hi) b = xp4[32 + lane];

    float s = a.x + a.y + a.z + a.w + b.x + b.y + b.z + b.w;
    #pragma unroll
    for (int o = 16; o; o >>= 1) s += __shfl_xor_sync(0xffffffffu, s, o);
    float mean = s * (1.f / 192.f);

    float q = (a.x - mean) * (a.x - mean) + (a.y - mean) * (a.y - mean)
            + (a.z - mean) * (a.z - mean) + (a.w - mean) * (a.w - mean);
    if (hi)
        q += (b.x - mean) * (b.x - mean) + (b.y - mean) * (b.y - mean)
           + (b.z - mean) * (b.z - mean) + (b.w - mean) * (b.w - mean);
    #pragma unroll
    for (int o = 16; o; o >>= 1) q += __shfl_xor_sync(0xffffffffu, q, o);
    float inv = rsqrtf(q * (1.f / 192.f) + EPSLN);

    const float4* g4 = (const float4*)gam;
    const float4* t4 = (const float4*)bet;
    bf16* op = out + (size_t)token * CC;

    {
        float4 g = g4[lane], t = t4[lane];
        bf164 r;
        r.a = __floats2bfloat162_rn((a.x - mean) * inv * g.x + t.x,
                                    (a.y - mean) * inv * g.y + t.y);
        r.b = __floats2bfloat162_rn((a.z - mean) * inv * g.z + t.z,
                                    (a.w - mean) * inv * g.w + t.w);
        ((bf164*)op)[lane] = r;
    }
    if (hi) {
        float4 g = g4[32 + lane], t = t4[32 + lane];
        bf164 r;
        r.a = __floats2bfloat162_rn((b.x - mean) * inv * g.x + t.x,
                                    (b.y - mean) * inv * g.y + t.y);
        r.b = __floats2bfloat162_rn((b.z - mean) * inv * g.z + t.z,
                                    (b.w - mean) * inv * g.w + t.w);
        ((bf164*)op)[32 + lane] = r;
    }
}

// ---------------- BF16 HMMA GEMM, 128x64 tile, 3-stage pipeline (R7) --------
#define ASTRIDE_B 80
#define BSTRIDE_B 144
#define A_STAGE   (128 * ASTRIDE_B)
#define B_STAGE   (32 * BSTRIDE_B)
#define STAGE_SZ  (A_STAGE + B_STAGE)
#define NSTAGE    3

template<int EPI, typename OutT>
__global__ void __launch_bounds__(256)
bgemm_kernel(const bf16* __restrict__ A,
             const bf16* __restrict__ W,
             const float* __restrict__ bias,
             const float* __restrict__ res,
             OutT* __restrict__ out,
             int N, int K) {
    __shared__ __align__(16) uint8_t smem[NSTAGE * STAGE_SZ];

    const int tid    = threadIdx.x;
    const int warp   = tid >> 5;
    const int lane   = tid & 31;
    const int warp_m = warp & 3;
    const int warp_n = warp >> 2;
    const int lr     = lane >> 2;
    const int lc     = lane & 3;

    const int mBlk = blockIdx.y * 128;
    const int nBlk = blockIdx.x * 64;

    const uint32_t sbase = (uint32_t)__cvta_generic_to_shared(smem);

    const int aRow = tid >> 2;
    const int bRow = tid >> 3;
    const bf16* gA = A + (size_t)(mBlk + aRow) * K + (tid & 3) * 8;
    const bf16* gB = W + (size_t)bRow * N + nBlk + (tid & 7) * 8;
    const uint32_t dA0 = sbase + aRow * ASTRIDE_B + (tid & 3) * 16;
    const uint32_t dB0 = sbase + A_STAGE + bRow * BSTRIDE_B + (tid & 7) * 16;

    const uint32_t aFragB = sbase + (warp_m * 32 + (lane & 15)) * ASTRIDE_B
                                  + (lane >> 4) * 16;
    const int grp = lane >> 3;
    const uint32_t bFragB = sbase + A_STAGE
                          + ((grp & 1) * 8 + (lane & 7)) * BSTRIDE_B
                          + (warp_n * 32 + (grp >> 1) * 8) * 2;

    float c[2][4][4];
    #pragma unroll
    for (int mt = 0; mt < 2; mt++)
        #pragma unroll
        for (int nt = 0; nt < 4; nt++)
            #pragma unroll
            for (int i = 0; i < 4; i++) c[mt][nt][i] = 0.f;

    const int iters = K >> 5;

    // prologue: stage 0 and 1 in flight
    #pragma unroll
    for (int p = 0; p < 2; p++) {
        uint32_t so = p * STAGE_SZ;
        cp16(dA0 + so, gA + p * 32);
        cp16(dA0 + so + 64 * ASTRIDE_B, gA + (size_t)64 * K + p * 32);
        cp16(dB0 + so, gB + (size_t)p * 32 * N);
        asm volatile("cp.async.commit_group;");
    }

    int stage = 0;                  // stage holding iteration `it`
    int wstage = 2;                 // stage to write iteration `it+2`
    for (int it = 0; it < iters; it++) {
        asm volatile("cp.async.wait_group 1;");   // stage for `it` resident
        __syncthreads();

        // issue load for it+2 (writes stage (it-1)%3, all readers passed barrier)
        if (it + 2 < iters) {
            const uint32_t sn = wstage * STAGE_SZ;
            cp16(dA0 + sn, gA + (it + 2) * 32);
            cp16(dA0 + sn + 64 * ASTRIDE_B, gA + (size_t)64 * K + (it + 2) * 32);
            cp16(dB0 + sn, gB + (size_t)(it + 2) * 32 * N);
        }
        asm volatile("cp.async.commit_group;");   // keep counts uniform

        const uint32_t so = stage * STAGE_SZ;
        #pragma unroll
        for (int ks = 0; ks < 2; ks++) {
            uint32_t af[2][4], bf[4][2];
            #pragma unroll
            for (int mt = 0; mt < 2; mt++)
                asm volatile(
                    "ldmatrix.sync.aligned.m8n8.x4.shared.b16 {%0,%1,%2,%3}, [%4];"
                    : "=r"(af[mt][0]), "=r"(af[mt][1]),
                      "=r"(af[mt][2]), "=r"(af[mt][3])
                    : "r"(aFragB + so + mt * (16 * ASTRIDE_B) + ks * 32));
            #pragma unroll
            for (int np = 0; np < 2; np++) {
                uint32_t r0, r1, r2, r3;
                asm volatile(
                    "ldmatrix.sync.aligned.m8n8.x4.trans.shared.b16 {%0,%1,%2,%3}, [%4];"
                    : "=r"(r0), "=r"(r1), "=r"(r2), "=r"(r3)
                    : "r"(bFragB + so + ks * (16 * BSTRIDE_B) + np * 32));
                bf[2 * np][0] = r0; bf[2 * np][1] = r1;
                bf[2 * np + 1][0] = r2; bf[2 * np + 1][1] = r3;
            }
            #pragma unroll
            for (int mt = 0; mt < 2; mt++)
                #pragma unroll
                for (int nt = 0; nt < 4; nt++)
                    asm volatile(
                        "mma.sync.aligned.m16n8k16.row.col.f32.bf16.bf16.f32 "
                        "{%0,%1,%2,%3}, {%4,%5,%6,%7}, {%8,%9}, {%0,%1,%2,%3};"
                        : "+f"(c[mt][nt][0]), "+f"(c[mt][nt][1]),
                          "+f"(c[mt][nt][2]), "+f"(c[mt][nt][3])
                        : "r"(af[mt][0]), "r"(af[mt][1]),
                          "r"(af[mt][2]), "r"(af[mt][3]),
                          "r"(bf[nt][0]), "r"(bf[nt][1]));
        }
        stage  = (stage == NSTAGE - 1) ? 0 : stage + 1;
        wstage = (wstage == NSTAGE - 1) ? 0 : wstage + 1;
    }

    // ---------------- epilogue ----------------
    #pragma unroll
    for (int mt = 0; mt < 2; mt++) {
        #pragma unroll
        for (int rr = 0; rr < 2; rr++) {
            int row = mBlk + warp_m * 32 + mt * 16 + lr + rr * 8;
            int trow = (EPI == 1) ? win_to_nat(row) : row;
            #pragma unroll
            for (int nt = 0; nt < 4; nt++) {
                int col = nBlk + warp_n * 32 + nt * 8 + lc * 2;
                float v0 = c[mt][nt][rr * 2 + 0] + bias[col];
                float v1 = c[mt][nt][rr * 2 + 1] + bias[col + 1];
                if (EPI == 1) {
                    const float* rp = res + (size_t)trow * CC + col;
                    v0 += rp[0]; v1 += rp[1];
                    float* op = (float*)out + (size_t)trow * CC + col;
                    op[0] = v0; op[1] = v1;
                } else if (EPI == 3) {
                    const float* rp = res + (size_t)row * CC + col;
                    v0 += rp[0]; v1 += rp[1];
                    float* op = (float*)out + (size_t)row * CC + col;
                    op[0] = v0; op[1] = v1;
                } else {
                    if (EPI == 2) {
                        v0 = 0.5f * v0 * (1.f + erff(v0 * 0.70710678118654752f));
                        v1 = 0.5f * v1 * (1.f + erff(v1 * 0.70710678118654752f));
                    }
                    __nv_bfloat162* op =
                        (__nv_bfloat162*)((bf16*)out + (size_t)row * N + col);
                    op[0] = __floats2bfloat162_rn(v0, v1);
                }
            }
        }
    }
}

// ---------------- tensor-core windowed attention ----------------------------
// one CTA per (window, head); 4 warps; 49 padded to 64. bias table in bf16.
__global__ void __launch_bounds__(128)
attn_kernel(const bf16* __restrict__ qkv,
            const bf16* __restrict__ btab,
            bf16* __restrict__ out) {
    __shared__ __align__(128) bf16 Qs[64 * 40];
    __shared__ __align__(128) bf16 Ks[64 * 40];
    __shared__ __align__(128) bf16 Vs[64 * 40];
    __shared__ __align__(128) bf16 Bsm[49 * 72];   // 144B row stride

    const int wt   = blockIdx.x / NHEAD;
    const int head = blockIdx.x - wt * NHEAD;
    const int tid  = threadIdx.x;
    const int warp = tid >> 5;
    const int lane = tid & 31;
    const int lr   = lane >> 2;
    const int lc   = lane & 3;

    const uint32_t sQ = (uint32_t)__cvta_generic_to_shared(Qs);
    const uint32_t sK = (uint32_t)__cvta_generic_to_shared(Ks);
    const uint32_t sV = (uint32_t)__cvta_generic_to_shared(Vs);
    const uint32_t sB = (uint32_t)__cvta_generic_to_shared(Bsm);

    // zero pad rows 49..63 of Q,K,V (15 rows * 80B each = 75 uint4)
    for (int i = tid; i < 225; i += 128) {
        int mat = i / 75, r = i - mat * 75;
        char* base = (char*)(mat == 0 ? Qs : (mat == 1 ? Ks : Vs));
        ((uint4*)(base + 49 * 80))[r] = make_uint4(0, 0, 0, 0);
    }

    // qkv: 3 mats * 49 rows * 4 chunks of 16B
    const bf16* qbase = qkv + (size_t)wt * 49 * 576 + head * 32;
    for (int i = tid; i < 588; i += 128) {
        int mat = i / 196, rem = i - mat * 196;
        int row = rem >> 2, ch = rem & 3;
        const bf16* src = qbase + (size_t)row * 576 + mat * 192 + ch * 8;
        uint32_t dst = (mat == 0 ? sQ : (mat == 1 ? sK : sV)) + row * 80 + ch * 16;
        cp16(dst, src);
    }
    // bias: 49 rows * 8 chunks of 16B (64 bf16/row), smem stride 144B
    const int w  = wt & 63;
    const int wh = w >> 3, ww = w & 7;
    const int cls = ((wh == 7) ? 2 : 0) | ((ww == 7) ? 1 : 0);
    const bf16* bsrc = btab + (size_t)(cls * NHEAD + head) * 49 * 64;
    for (int i = tid; i < 392; i += 128) {
        int row = i >> 3, ch = i & 7;
        cp16(sB + row * 144 + ch * 16, bsrc + row * 64 + ch * 8);
    }
    asm volatile("cp.async.commit_group;\ncp.async.wait_group 0;");
    __syncthreads();

    // ---- S = Q @ K^T : warp band of 16 rows x 64 cols ----
    uint32_t qa[2][4];
    #pragma unroll
    for (int ks = 0; ks < 2; ks++) {
        uint32_t addr = sQ + (warp * 16 + (lane & 15)) * 80 + ks * 32 + (lane >> 4) * 16;
        asm volatile("ldmatrix.sync.aligned.m8n8.x4.shared.b16 {%0,%1,%2,%3}, [%4];"
                     : "=r"(qa[ks][0]), "=r"(qa[ks][1]), "=r"(qa[ks][2]), "=r"(qa[ks][3])
                     : "r"(addr));
    }
    uint32_t kb[8][2][2];
    #pragma unroll
    for (int kp = 0; kp < 4; kp++)
        #pragma unroll
        for (int ks = 0; ks < 2; ks++) {
            uint32_t r0, r1, r2, r3;
            uint32_t addr = sK + (kp * 16 + (lane & 15)) * 80 + ks * 32 + (lane >> 4) * 16;
            asm volatile("ldmatrix.sync.aligned.m8n8.x4.shared.b16 {%0,%1,%2,%3}, [%4];"
                         : "=r"(r0), "=r"(r1), "=r"(r2), "=r"(r3) : "r"(addr));
            kb[2 * kp][ks][0] = r0;     kb[2 * kp][ks][1] = r2;
            kb[2 * kp + 1][ks][0] = r1; kb[2 * kp + 1][ks][1] = r3;
        }

    float c[8][4];
    #pragma unroll
    for (int j = 0; j < 8; j++)
        #pragma unroll
        for (int i = 0; i < 4; i++) c[j][i] = 0.f;
    #pragma unroll
    for (int j = 0; j < 8; j++)
        #pragma unroll
        for (int ks = 0; ks < 2; ks++)
            asm volatile(
                "mma.sync.aligned.m16n8k16.row.col.f32.bf16.bf16.f32 "
                "{%0,%1,%2,%3}, {%4,%5,%6,%7}, {%8,%9}, {%0,%1,%2,%3};"
                : "+f"(c[j][0]), "+f"(c[j][1]), "+f"(c[j][2]), "+f"(c[j][3])
                : "r"(qa[ks][0]), "r"(qa[ks][1]), "r"(qa[ks][2]), "r"(qa[ks][3]),
                  "r"(kb[j][ks][0]), "r"(kb[j][ks][1]));

    // ---- bias + mask + softmax (registers) ----
    const float scale = 0.17677669529663687f;
    const int r0c = min(warp * 16 + lr, 48);
    const int r1c = min(warp * 16 + lr + 8, 48);
    const __nv_bfloat162* b0p = (const __nv_bfloat162*)(Bsm + r0c * 72) + lc;
    const __nv_bfloat162* b1p = (const __nv_bfloat162*)(Bsm + r1c * 72) + lc;
    float mx0 = -1e30f, mx1 = -1e30f;
    #pragma unroll
    for (int j = 0; j < 8; j++) {
        float2 bb0 = __bfloat1622float2(b0p[4 * j]);
        float2 bb1 = __bfloat1622float2(b1p[4 * j]);
        c[j][0] = fmaf(c[j][0], scale, bb0.x);
        c[j][1] = fmaf(c[j][1], scale, bb0.y);
        c[j][2] = fmaf(c[j][2], scale, bb1.x);
        c[j][3] = fmaf(c[j][3], scale, bb1.y);
        mx0 = fmaxf(mx0, fmaxf(c[j][0], c[j][1]));
        mx1 = fmaxf(mx1, fmaxf(c[j][2], c[j][3]));
    }
    mx0 = fmaxf(mx0, __shfl_xor_sync(0xffffffffu, mx0, 1));
    mx0 = fmaxf(mx0, __shfl_xor_sync(0xffffffffu, mx0, 2));
    mx1 = fmaxf(mx1, __shfl_xor_sync(0xffffffffu, mx1, 1));
    mx1 = fmaxf(mx1, __shfl_xor_sync(0xffffffffu, mx1, 2));
    float s0 = 0.f, s1 = 0.f;
    #pragma unroll
    for (int j = 0; j < 8; j++) {
        c[j][0] = __expf(c[j][0] - mx0); s0 += c[j][0];
        c[j][1] = __expf(c[j][1] - mx0); s0 += c[j][1];
        c[j][2] = __expf(c[j][2] - mx1); s1 += c[j][2];
        c[j][3] = __expf(c[j][3] - mx1); s1 += c[j][3];
    }
    s0 += __shfl_xor_sync(0xffffffffu, s0, 1);
    s0 += __shfl_xor_sync(0xffffffffu, s0, 2);
    s1 += __shfl_xor_sync(0xffffffffu, s1, 1);
    s1 += __shfl_xor_sync(0xffffffffu, s1, 2);
    const float inv0 = 1.f / s0, inv1 = 1.f / s1;

    // ---- O = P @ V ----
    uint32_t pa[4][4];
    #pragma unroll
    for (int t = 0; t < 4; t++) {
        pa[t][0] = pack_bf2(c[2 * t][0] * inv0, c[2 * t][1] * inv0);
        pa[t][1] = pack_bf2(c[2 * t][2] * inv1, c[2 * t][3] * inv1);
        pa[t][2] = pack_bf2(c[2 * t + 1][0] * inv0, c[2 * t + 1][1] * inv0);
        pa[t][3] = pack_bf2(c[2 * t + 1][2] * inv1, c[2 * t + 1][3] * inv1);
    }
    float o[4][4];
    #pragma unroll
    for (int nt = 0; nt < 4; nt++)
        #pragma unroll
        for (int i = 0; i < 4; i++) o[nt][i] = 0.f;
    const int grp = lane >> 3;
    #pragma unroll
    for (int t = 0; t < 4; t++) {
        uint32_t vb[4][2];
        #pragma unroll
        for (int np = 0; np < 2; np++) {
            uint32_t r0, r1, r2, r3;
            uint32_t addr = sV + (t * 16 + (grp & 1) * 8 + (lane & 7)) * 80
                               + (grp >> 1) * 16 + np * 32;
            asm volatile("ldmatrix.sync.aligned.m8n8.x4.trans.shared.b16 {%0,%1,%2,%3}, [%4];"
                         : "=r"(r0), "=r"(r1), "=r"(r2), "=r"(r3) : "r"(addr));
            vb[2 * np][0] = r0;     vb[2 * np][1] = r1;
            vb[2 * np + 1][0] = r2; vb[2 * np + 1][1] = r3;
        }
        #pragma unroll
        for (int nt = 0; nt < 4; nt++)
            asm volatile(
                "mma.sync.aligned.m16n8k16.row.col.f32.bf16.bf16.f32 "
                "{%0,%1,%2,%3}, {%4,%5,%6,%7}, {%8,%9}, {%0,%1,%2,%3};"
                : "+f"(o[nt][0]), "+f"(o[nt][1]), "+f"(o[nt][2]), "+f"(o[nt][3])
                : "r"(pa[t][0]), "r"(pa[t][1]), "r"(pa[t][2]), "r"(pa[t][3]),
                  "r"(vb[nt][0]), "r"(vb[nt][1]));
    }

    // ---- store O rows < 49 ----
    bf16* obase = out + (size_t)wt * 49 * CC + head * 32;
    #pragma unroll
    for (int half = 0; half < 2; half++) {
        int r = warp * 16 + lr + half * 8;
        if (r < 49) {
            #pragma unroll
            for (int nt = 0; nt < 4; nt++) {
                int d = nt * 8 + 2 * lc;
                *(__nv_bfloat162*)(obase + (size_t)r * CC + d) =
                    __floats2bfloat162_rn(o[nt][2 * half], o[nt][2 * half + 1]);
            }
        }
    }
}

// ---------------- launch ----------------------------------------------------
extern "C" void kernel_launch(void* const* d_in, const int* in_sizes, int n_in,
                              void* d_out, int out_size) {
    const float* x      = (const float*)d_in[0];
    const float* n1g    = (const float*)d_in[1];
    const float* n1b    = (const float*)d_in[2];
    const float* qkv_w  = (const float*)d_in[3];
    const float* qkv_b  = (const float*)d_in[4];
    const float* rpb    = (const float*)d_in[5];
    const float* proj_w = (const float*)d_in[6];
    const float* proj_b = (const float*)d_in[7];
    const float* n2g    = (const float*)d_in[8];
    const float* n2b    = (const float*)d_in[9];
    const float* fc1_w  = (const float*)d_in[10];
    const float* fc1_b  = (const float*)d_in[11];
    const float* fc2_w  = (const float*)d_in[12];
    const float* fc2_b  = (const float*)d_in[13];
    float* out = (float*)d_out;

    bf16 *xw, *qkv, *att, *xn2, *h1, *wq, *wp, *w1, *w2, *bias;
    float *y;
    cudaGetSymbolAddress((void**)&xw,  g_xw);
    cudaGetSymbolAddress((void**)&qkv, g_qkv);
    cudaGetSymbolAddress((void**)&att, g_att);
    cudaGetSymbolAddress((void**)&y,   g_y);
    cudaGetSymbolAddress((void**)&xn2, g_xn2);
    cudaGetSymbolAddress((void**)&h1,  g_h1);
    cudaGetSymbolAddress((void**)&wq,  g_wq);
    cudaGetSymbolAddress((void**)&wp,  g_wp);
    cudaGetSymbolAddress((void**)&w1,  g_w1);
    cudaGetSymbolAddress((void**)&w2,  g_w2);
    cudaGetSymbolAddress((void**)&bias, g_bias);

    // 0. weight conversion (1 launch) + bias/mask tables
    cvt_all_kernel<<<432, 256>>>(qkv_w, proj_w, fc1_w, fc2_w, wq, wp, w1, w2);
    bias_kernel<<<24, 256>>>(rpb, bias);

    // 1. LN1 + cyclic shift + window partition (bf16 out)
    ln_kernel<true><<<TOK / 8, 256>>>(x, n1g, n1b, xw);
    // 2. QKV projection
    bgemm_kernel<0, bf16><<<dim3(9, TOK / 128), 256>>>(xw, wq, qkv_b, nullptr, qkv, 576, 192);
    // 3. tensor-core windowed attention
    attn_kernel<<<2048 * NHEAD, 128>>>(qkv, bias, att);
    // 4. proj + inverse shift + residual (f32 out)
    bgemm_kernel<1, float><<<dim3(3, TOK / 128), 256>>>(att, wp, proj_b, x, y, 192, 192);
    // 5. LN2 (bf16 out)
    ln_kernel<false><<<TOK / 8, 256>>>(y, n2g, n2b, xn2);
    // 6. FC1 + GELU (bf16 out)
    bgemm_kernel<2, bf16><<<dim3(12, TOK / 128), 256>>>(xn2, w1, fc1_b, nullptr, h1, 768, 192);
    // 7. FC2 + residual -> output (f32)
    bgemm_kernel<3, float><<<dim3(3, TOK / 128), 256>>>(h1, w2, fc2_b, y, out, 192, 768);
}

// round 17
// speedup vs baseline: 1.0219x; 1.0219x over previous
#include <cuda_runtime.h>
#include <cuda_bf16.h>
#include <math.h>
#include <stdint.h>

#define TOK   100352          // B*H*W = 32*56*56
#define CC    192
#define NHEAD 6
#define EPSLN 1e-5f

typedef __nv_bfloat16 bf16;

// pack two floats into one bf16x2 register word (lo = first, hi = second)
__device__ __forceinline__ uint32_t pack_bf2(float a, float b) {
    __nv_bfloat162 h = __floats2bfloat162_rn(a, b);
    __nv_bfloat162_raw r = *reinterpret_cast<__nv_bfloat162_raw*>(&h);
    return (uint32_t)r.x | ((uint32_t)r.y << 16);
}

// ---------------- scratch ---------------------------------------------------
__device__ bf16  g_xw [(size_t)TOK * CC];
__device__ bf16  g_qkv[(size_t)TOK * 576];
__device__ bf16  g_att[(size_t)TOK * CC];
__device__ float g_y  [(size_t)TOK * CC];
__device__ bf16  g_xn2[(size_t)TOK * CC];
__device__ bf16  g_h1 [(size_t)TOK * 768];
__device__ bf16  g_wq [192 * 576];
__device__ bf16  g_wp [192 * 192];
__device__ bf16  g_w1 [192 * 768];
__device__ bf16  g_w2 [768 * 192];
__device__ bf16  g_bias[24 * 49 * 64];   // [cls*6+head][n][m] rpb+mask (bf16)

// window-token index -> natural token index (cyclic shift +3)
__device__ __forceinline__ int win_to_nat(int o) {
    int b    = o / 3136;
    int r    = o - b * 3136;
    int w    = r / 49;
    int cell = r - w * 49;
    int wh = w >> 3, ww = w & 7;
    int i = cell / 7, j = cell - 7 * (cell / 7);
    int h  = wh * 7 + i + 3; if (h  >= 56) h  -= 56;
    int w2 = ww * 7 + j + 3; if (w2 >= 56) w2 -= 56;
    return b * 3136 + h * 56 + w2;
}

__device__ __forceinline__ void cp16(uint32_t dst, const void* src) {
    asm volatile("cp.async.cg.shared.global [%0], [%1], 16;" :: "r"(dst), "l"(src));
}

// ---------------- fused weight f32 -> bf16 ----------------------------------
__global__ void cvt_all_kernel(const float* __restrict__ w0, const float* __restrict__ w1,
                               const float* __restrict__ w2, const float* __restrict__ w3,
                               bf16* o0, bf16* o1, bf16* o2, bf16* o3) {
    int i = blockIdx.x * 256 + threadIdx.x;       // 110592 quads total
    const float* src; bf16* dst; int off;
    if (i < 27648)      { src = w0; dst = o0; off = i; }
    else if (i < 36864) { src = w1; dst = o1; off = i - 27648; }
    else if (i < 73728) { src = w2; dst = o2; off = i - 36864; }
    else                { src = w3; dst = o3; off = i - 73728; }
    float4 v = ((const float4*)src)[off];
    __nv_bfloat162* p = (__nv_bfloat162*)dst;
    p[2 * off + 0] = __floats2bfloat162_rn(v.x, v.y);
    p[2 * off + 1] = __floats2bfloat162_rn(v.z, v.w);
}

// ---------------- bias table: rpb gather + analytic shift mask (bf16) -------
__global__ void bias_kernel(const float* __restrict__ rpb, bf16* __restrict__ btab) {
    int cls  = blockIdx.x / 6;
    int head = blockIdx.x - cls * 6;
    int clsH = cls >> 1, clsW = cls & 1;
    for (int idx = threadIdx.x; idx < 49 * 64; idx += 256) {
        int n = idx >> 6, m = idx & 63;
        float v;
        if (m < 49) {
            int i1 = n / 7, j1 = n - 7 * i1;
            int i2 = m / 7, j2 = m - 7 * i2;
            v = rpb[((i1 - i2 + 6) * 13 + (j1 - j2 + 6)) * NHEAD + head];
            int ra = clsH ? (i1 < 4 ? 1 : 2) : 0;
            int rb = clsW ? (j1 < 4 ? 1 : 2) : 0;
            int ca = clsH ? (i2 < 4 ? 1 : 2) : 0;
            int cb = clsW ? (j2 < 4 ? 1 : 2) : 0;
            if (3 * ra + rb != 3 * ca + cb) v -= 100.f;
        } else v = -1e30f;
        btab[(size_t)blockIdx.x * 49 * 64 + idx] = __float2bfloat16(v);
    }
}

// ---------------- LayerNorm (one warp per token), bf16 out ------------------
template<bool GATHER>
__global__ void ln_kernel(const float* __restrict__ x,
                          const float* __restrict__ gam,
                          const float* __restrict__ bet,
                          bf16* __restrict__ out) {
    int token = blockIdx.x * 8 + (threadIdx.x >> 5);
    int lane  = threadIdx.x & 31;
    int src   = GATHER ? win_to_nat(token) : token;
    const float* xp = x + (size_t)src * CC;
    float v[6];
    float s = 0.f;
    #pragma unroll
    for (int u = 0; u < 6; u++) { v[u] = xp[lane + 32 * u]; s += v[u]; }
    #pragma unroll
    for (int o = 16; o; o >>= 1) s += __shfl_xor_sync(0xffffffffu, s, o);
    float mean = s * (1.f / 192.f);
    float q = 0.f;
    #pragma unroll
    for (int u = 0; u < 6; u++) { float d = v[u] - mean; q += d * d; }
    #pragma unroll
    for (int o = 16; o; o >>= 1) q += __shfl_xor_sync(0xffffffffu, q, o);
    float inv = rsqrtf(q * (1.f / 192.f) + EPSLN);
    bf16* op = out + (size_t)token * CC;
    #pragma unroll
    for (int u = 0; u < 6; u++) {
        int c = lane + 32 * u;
        op[c] = __float2bfloat16((v[u] - mean) * inv * gam[c] + bet[c]);
    }
}

// ---------------- BF16 HMMA GEMM, 128x64 tile, 3-stage, 4 CTAs/SM -----------
#define ASTRIDE_B 80
#define BSTRIDE_B 144
#define A_STAGE   (128 * ASTRIDE_B)
#define B_STAGE   (32 * BSTRIDE_B)
#define STAGE_SZ  (A_STAGE + B_STAGE)
#define NSTAGE    3

template<int EPI, typename OutT>
__global__ void __launch_bounds__(256, 4)
bgemm_kernel(const bf16* __restrict__ A,
             const bf16* __restrict__ W,
             const float* __restrict__ bias,
             const float* __restrict__ res,
             OutT* __restrict__ out,
             int N, int K) {
    __shared__ __align__(16) uint8_t smem[NSTAGE * STAGE_SZ];

    const int tid    = threadIdx.x;
    const int warp   = tid >> 5;
    const int lane   = tid & 31;
    const int warp_m = warp & 3;
    const int warp_n = warp >> 2;
    const int lr     = lane >> 2;
    const int lc     = lane & 3;

    const int mBlk = blockIdx.y * 128;
    const int nBlk = blockIdx.x * 64;

    const uint32_t sbase = (uint32_t)__cvta_generic_to_shared(smem);

    const int aRow = tid >> 2;
    const int bRow = tid >> 3;
    const bf16* gA = A + (size_t)(mBlk + aRow) * K + (tid & 3) * 8;
    const bf16* gB = W + (size_t)bRow * N + nBlk + (tid & 7) * 8;
    const uint32_t dA0 = sbase + aRow * ASTRIDE_B + (tid & 3) * 16;
    const uint32_t dB0 = sbase + A_STAGE + bRow * BSTRIDE_B + (tid & 7) * 16;

    const uint32_t aFragB = sbase + (warp_m * 32 + (lane & 15)) * ASTRIDE_B
                                  + (lane >> 4) * 16;
    const int grp = lane >> 3;
    const uint32_t bFragB = sbase + A_STAGE
                          + ((grp & 1) * 8 + (lane & 7)) * BSTRIDE_B
                          + (warp_n * 32 + (grp >> 1) * 8) * 2;

    float c[2][4][4];
    #pragma unroll
    for (int mt = 0; mt < 2; mt++)
        #pragma unroll
        for (int nt = 0; nt < 4; nt++)
            #pragma unroll
            for (int i = 0; i < 4; i++) c[mt][nt][i] = 0.f;

    const int iters = K >> 5;

    // prologue: stage 0 and 1 in flight
    #pragma unroll
    for (int p = 0; p < 2; p++) {
        uint32_t so = p * STAGE_SZ;
        cp16(dA0 + so, gA + p * 32);
        cp16(dA0 + so + 64 * ASTRIDE_B, gA + (size_t)64 * K + p * 32);
        cp16(dB0 + so, gB + (size_t)p * 32 * N);
        asm volatile("cp.async.commit_group;");
    }

    int stage = 0;                  // stage holding iteration `it`
    int wstage = 2;                 // stage to write iteration `it+2`
    for (int it = 0; it < iters; it++) {
        asm volatile("cp.async.wait_group 1;");   // stage for `it` resident
        __syncthreads();

        // issue load for it+2 (writes stage (it-1)%3, all readers passed barrier)
        if (it + 2 < iters) {
            const uint32_t sn = wstage * STAGE_SZ;
            cp16(dA0 + sn, gA + (it + 2) * 32);
            cp16(dA0 + sn + 64 * ASTRIDE_B, gA + (size_t)64 * K + (it + 2) * 32);
            cp16(dB0 + sn, gB + (size_t)(it + 2) * 32 * N);
        }
        asm volatile("cp.async.commit_group;");   // keep counts uniform

        const uint32_t so = stage * STAGE_SZ;
        #pragma unroll
        for (int ks = 0; ks < 2; ks++) {
            uint32_t af[2][4], bf[4][2];
            #pragma unroll
            for (int mt = 0; mt < 2; mt++)
                asm volatile(
                    "ldmatrix.sync.aligned.m8n8.x4.shared.b16 {%0,%1,%2,%3}, [%4];"
                    : "=r"(af[mt][0]), "=r"(af[mt][1]),
                      "=r"(af[mt][2]), "=r"(af[mt][3])
                    : "r"(aFragB + so + mt * (16 * ASTRIDE_B) + ks * 32));
            #pragma unroll
            for (int np = 0; np < 2; np++) {
                uint32_t r0, r1, r2, r3;
                asm volatile(
                    "ldmatrix.sync.aligned.m8n8.x4.trans.shared.b16 {%0,%1,%2,%3}, [%4];"
                    : "=r"(r0), "=r"(r1), "=r"(r2), "=r"(r3)
                    : "r"(bFragB + so + ks * (16 * BSTRIDE_B) + np * 32));
                bf[2 * np][0] = r0; bf[2 * np][1] = r1;
                bf[2 * np + 1][0] = r2; bf[2 * np + 1][1] = r3;
            }
            #pragma unroll
            for (int mt = 0; mt < 2; mt++)
                #pragma unroll
                for (int nt = 0; nt < 4; nt++)
                    asm volatile(
                        "mma.sync.aligned.m16n8k16.row.col.f32.bf16.bf16.f32 "
                        "{%0,%1,%2,%3}, {%4,%5,%6,%7}, {%8,%9}, {%0,%1,%2,%3};"
                        : "+f"(c[mt][nt][0]), "+f"(c[mt][nt][1]),
                          "+f"(c[mt][nt][2]), "+f"(c[mt][nt][3])
                        : "r"(af[mt][0]), "r"(af[mt][1]),
                          "r"(af[mt][2]), "r"(af[mt][3]),
                          "r"(bf[nt][0]), "r"(bf[nt][1]));
        }
        stage  = (stage == NSTAGE - 1) ? 0 : stage + 1;
        wstage = (wstage == NSTAGE - 1) ? 0 : wstage + 1;
    }

    // ---------------- epilogue ----------------
    #pragma unroll
    for (int mt = 0; mt < 2; mt++) {
        #pragma unroll
        for (int rr = 0; rr < 2; rr++) {
            int row = mBlk + warp_m * 32 + mt * 16 + lr + rr * 8;
            int trow = (EPI == 1) ? win_to_nat(row) : row;
            #pragma unroll
            for (int nt = 0; nt < 4; nt++) {
                int col = nBlk + warp_n * 32 + nt * 8 + lc * 2;
                float v0 = c[mt][nt][rr * 2 + 0] + bias[col];
                float v1 = c[mt][nt][rr * 2 + 1] + bias[col + 1];
                if (EPI == 1) {
                    const float* rp = res + (size_t)trow * CC + col;
                    v0 += rp[0]; v1 += rp[1];
                    float* op = (float*)out + (size_t)trow * CC + col;
                    op[0] = v0; op[1] = v1;
                } else if (EPI == 3) {
                    const float* rp = res + (size_t)row * CC + col;
                    v0 += rp[0]; v1 += rp[1];
                    float* op = (float*)out + (size_t)row * CC + col;
                    op[0] = v0; op[1] = v1;
                } else {
                    if (EPI == 2) {
                        v0 = 0.5f * v0 * (1.f + erff(v0 * 0.70710678118654752f));
                        v1 = 0.5f * v1 * (1.f + erff(v1 * 0.70710678118654752f));
                    }
                    __nv_bfloat162* op =
                        (__nv_bfloat162*)((bf16*)out + (size_t)row * N + col);
                    op[0] = __floats2bfloat162_rn(v0, v1);
                }
            }
        }
    }
}

// ---------------- tensor-core windowed attention ----------------------------
// one CTA per (window, head); 4 warps; 49 padded to 64. bias table in bf16.
__global__ void __launch_bounds__(128)
attn_kernel(const bf16* __restrict__ qkv,
            const bf16* __restrict__ btab,
            bf16* __restrict__ out) {
    __shared__ __align__(128) bf16 Qs[64 * 40];
    __shared__ __align__(128) bf16 Ks[64 * 40];
    __shared__ __align__(128) bf16 Vs[64 * 40];
    __shared__ __align__(128) bf16 Bsm[49 * 72];   // 144B row stride

    const int wt   = blockIdx.x / NHEAD;
    const int head = blockIdx.x - wt * NHEAD;
    const int tid  = threadIdx.x;
    const int warp = tid >> 5;
    const int lane = tid & 31;
    const int lr   = lane >> 2;
    const int lc   = lane & 3;

    const uint32_t sQ = (uint32_t)__cvta_generic_to_shared(Qs);
    const uint32_t sK = (uint32_t)__cvta_generic_to_shared(Ks);
    const uint32_t sV = (uint32_t)__cvta_generic_to_shared(Vs);
    const uint32_t sB = (uint32_t)__cvta_generic_to_shared(Bsm);

    // zero pad rows 49..63 of Q,K,V (15 rows * 80B each = 75 uint4)
    for (int i = tid; i < 225; i += 128) {
        int mat = i / 75, r = i - mat * 75;
        char* base = (char*)(mat == 0 ? Qs : (mat == 1 ? Ks : Vs));
        ((uint4*)(base + 49 * 80))[r] = make_uint4(0, 0, 0, 0);
    }

    // qkv: 3 mats * 49 rows * 4 chunks of 16B
    const bf16* qbase = qkv + (size_t)wt * 49 * 576 + head * 32;
    for (int i = tid; i < 588; i += 128) {
        int mat = i / 196, rem = i - mat * 196;
        int row = rem >> 2, ch = rem & 3;
        const bf16* src = qbase + (size_t)row * 576 + mat * 192 + ch * 8;
        uint32_t dst = (mat == 0 ? sQ : (mat == 1 ? sK : sV)) + row * 80 + ch * 16;
        cp16(dst, src);
    }
    // bias: 49 rows * 8 chunks of 16B (64 bf16/row), smem stride 144B
    const int w  = wt & 63;
    const int wh = w >> 3, ww = w & 7;
    const int cls = ((wh == 7) ? 2 : 0) | ((ww == 7) ? 1 : 0);
    const bf16* bsrc = btab + (size_t)(cls * NHEAD + head) * 49 * 64;
    for (int i = tid; i < 392; i += 128) {
        int row = i >> 3, ch = i & 7;
        cp16(sB + row * 144 + ch * 16, bsrc + row * 64 + ch * 8);
    }
    asm volatile("cp.async.commit_group;\ncp.async.wait_group 0;");
    __syncthreads();

    // ---- S = Q @ K^T : warp band of 16 rows x 64 cols ----
    uint32_t qa[2][4];
    #pragma unroll
    for (int ks = 0; ks < 2; ks++) {
        uint32_t addr = sQ + (warp * 16 + (lane & 15)) * 80 + ks * 32 + (lane >> 4) * 16;
        asm volatile("ldmatrix.sync.aligned.m8n8.x4.shared.b16 {%0,%1,%2,%3}, [%4];"
                     : "=r"(qa[ks][0]), "=r"(qa[ks][1]), "=r"(qa[ks][2]), "=r"(qa[ks][3])
                     : "r"(addr));
    }
    uint32_t kb[8][2][2];
    #pragma unroll
    for (int kp = 0; kp < 4; kp++)
        #pragma unroll
        for (int ks = 0; ks < 2; ks++) {
            uint32_t r0, r1, r2, r3;
            uint32_t addr = sK + (kp * 16 + (lane & 15)) * 80 + ks * 32 + (lane >> 4) * 16;
            asm volatile("ldmatrix.sync.aligned.m8n8.x4.shared.b16 {%0,%1,%2,%3}, [%4];"
                         : "=r"(r0), "=r"(r1), "=r"(r2), "=r"(r3) : "r"(addr));
            kb[2 * kp][ks][0] = r0;     kb[2 * kp][ks][1] = r2;
            kb[2 * kp + 1][ks][0] = r1; kb[2 * kp + 1][ks][1] = r3;
        }

    float c[8][4];
    #pragma unroll
    for (int j = 0; j < 8; j++)
        #pragma unroll
        for (int i = 0; i < 4; i++) c[j][i] = 0.f;
    #pragma unroll
    for (int j = 0; j < 8; j++)
        #pragma unroll
        for (int ks = 0; ks < 2; ks++)
            asm volatile(
                "mma.sync.aligned.m16n8k16.row.col.f32.bf16.bf16.f32 "
                "{%0,%1,%2,%3}, {%4,%5,%6,%7}, {%8,%9}, {%0,%1,%2,%3};"
                : "+f"(c[j][0]), "+f"(c[j][1]), "+f"(c[j][2]), "+f"(c[j][3])
                : "r"(qa[ks][0]), "r"(qa[ks][1]), "r"(qa[ks][2]), "r"(qa[ks][3]),
                  "r"(kb[j][ks][0]), "r"(kb[j][ks][1]));

    // ---- bias + mask + softmax (registers) ----
    const float scale = 0.17677669529663687f;
    const int r0c = min(warp * 16 + lr, 48);
    const int r1c = min(warp * 16 + lr + 8, 48);
    const __nv_bfloat162* b0p = (const __nv_bfloat162*)(Bsm + r0c * 72) + lc;
    const __nv_bfloat162* b1p = (const __nv_bfloat162*)(Bsm + r1c * 72) + lc;
    float mx0 = -1e30f, mx1 = -1e30f;
    #pragma unroll
    for (int j = 0; j < 8; j++) {
        float2 bb0 = __bfloat1622float2(b0p[4 * j]);
        float2 bb1 = __bfloat1622float2(b1p[4 * j]);
        c[j][0] = fmaf(c[j][0], scale, bb0.x);
        c[j][1] = fmaf(c[j][1], scale, bb0.y);
        c[j][2] = fmaf(c[j][2], scale, bb1.x);
        c[j][3] = fmaf(c[j][3], scale, bb1.y);
        mx0 = fmaxf(mx0, fmaxf(c[j][0], c[j][1]));
        mx1 = fmaxf(mx1, fmaxf(c[j][2], c[j][3]));
    }
    mx0 = fmaxf(mx0, __shfl_xor_sync(0xffffffffu, mx0, 1));
    mx0 = fmaxf(mx0, __shfl_xor_sync(0xffffffffu, mx0, 2));
    mx1 = fmaxf(mx1, __shfl_xor_sync(0xffffffffu, mx1, 1));
    mx1 = fmaxf(mx1, __shfl_xor_sync(0xffffffffu, mx1, 2));
    float s0 = 0.f, s1 = 0.f;
    #pragma unroll
    for (int j = 0; j < 8; j++) {
        c[j][0] = __expf(c[j][0] - mx0); s0 += c[j][0];
        c[j][1] = __expf(c[j][1] - mx0); s0 += c[j][1];
        c[j][2] = __expf(c[j][2] - mx1); s1 += c[j][2];
        c[j][3] = __expf(c[j][3] - mx1); s1 += c[j][3];
    }
    s0 += __shfl_xor_sync(0xffffffffu, s0, 1);
    s0 += __shfl_xor_sync(0xffffffffu, s0, 2);
    s1 += __shfl_xor_sync(0xffffffffu, s1, 1);
    s1 += __shfl_xor_sync(0xffffffffu, s1, 2);
    const float inv0 = 1.f / s0, inv1 = 1.f / s1;

    // ---- O = P @ V ----
    uint32_t pa[4][4];
    #pragma unroll
    for (int t = 0; t < 4; t++) {
        pa[t][0] = pack_bf2(c[2 * t][0] * inv0, c[2 * t][1] * inv0);
        pa[t][1] = pack_bf2(c[2 * t][2] * inv1, c[2 * t][3] * inv1);
        pa[t][2] = pack_bf2(c[2 * t + 1][0] * inv0, c[2 * t + 1][1] * inv0);
        pa[t][3] = pack_bf2(c[2 * t + 1][2] * inv1, c[2 * t + 1][3] * inv1);
    }
    float o[4][4];
    #pragma unroll
    for (int nt = 0; nt < 4; nt++)
        #pragma unroll
        for (int i = 0; i < 4; i++) o[nt][i] = 0.f;
    const int grp = lane >> 3;
    #pragma unroll
    for (int t = 0; t < 4; t++) {
        uint32_t vb[4][2];
        #pragma unroll
        for (int np = 0; np < 2; np++) {
            uint32_t r0, r1, r2, r3;
            uint32_t addr = sV + (t * 16 + (grp & 1) * 8 + (lane & 7)) * 80
                               + (grp >> 1) * 16 + np * 32;
            asm volatile("ldmatrix.sync.aligned.m8n8.x4.trans.shared.b16 {%0,%1,%2,%3}, [%4];"
                         : "=r"(r0), "=r"(r1), "=r"(r2), "=r"(r3) : "r"(addr));
            vb[2 * np][0] = r0;     vb[2 * np][1] = r1;
            vb[2 * np + 1][0] = r2; vb[2 * np + 1][1] = r3;
        }
        #pragma unroll
        for (int nt = 0; nt < 4; nt++)
            asm volatile(
                "mma.sync.aligned.m16n8k16.row.col.f32.bf16.bf16.f32 "
                "{%0,%1,%2,%3}, {%4,%5,%6,%7}, {%8,%9}, {%0,%1,%2,%3};"
                : "+f"(o[nt][0]), "+f"(o[nt][1]), "+f"(o[nt][2]), "+f"(o[nt][3])
                : "r"(pa[t][0]), "r"(pa[t][1]), "r"(pa[t][2]), "r"(pa[t][3]),
                  "r"(vb[nt][0]), "r"(vb[nt][1]));
    }

    // ---- store O rows < 49 ----
    bf16* obase = out + (size_t)wt * 49 * CC + head * 32;
    #pragma unroll
    for (int half = 0; half < 2; half++) {
        int r = warp * 16 + lr + half * 8;
        if (r < 49) {
            #pragma unroll
            for (int nt = 0; nt < 4; nt++) {
                int d = nt * 8 + 2 * lc;
                *(__nv_bfloat162*)(obase + (size_t)r * CC + d) =
                    __floats2bfloat162_rn(o[nt][2 * half], o[nt][2 * half + 1]);
            }
        }
    }
}

// ---------------- launch ----------------------------------------------------
extern "C" void kernel_launch(void* const* d_in, const int* in_sizes, int n_in,
                              void* d_out, int out_size) {
    const float* x      = (const float*)d_in[0];
    const float* n1g    = (const float*)d_in[1];
    const float* n1b    = (const float*)d_in[2];
    const float* qkv_w  = (const float*)d_in[3];
    const float* qkv_b  = (const float*)d_in[4];
    const float* rpb    = (const float*)d_in[5];
    const float* proj_w = (const float*)d_in[6];
    const float* proj_b = (const float*)d_in[7];
    const float* n2g    = (const float*)d_in[8];
    const float* n2b    = (const float*)d_in[9];
    const float* fc1_w  = (const float*)d_in[10];
    const float* fc1_b  = (const float*)d_in[11];
    const float* fc2_w  = (const float*)d_in[12];
    const float* fc2_b  = (const float*)d_in[13];
    float* out = (float*)d_out;

    bf16 *xw, *qkv, *att, *xn2, *h1, *wq, *wp, *w1, *w2, *bias;
    float *y;
    cudaGetSymbolAddress((void**)&xw,  g_xw);
    cudaGetSymbolAddress((void**)&qkv, g_qkv);
    cudaGetSymbolAddress((void**)&att, g_att);
    cudaGetSymbolAddress((void**)&y,   g_y);
    cudaGetSymbolAddress((void**)&xn2, g_xn2);
    cudaGetSymbolAddress((void**)&h1,  g_h1);
    cudaGetSymbolAddress((void**)&wq,  g_wq);
    cudaGetSymbolAddress((void**)&wp,  g_wp);
    cudaGetSymbolAddress((void**)&w1,  g_w1);
    cudaGetSymbolAddress((void**)&w2,  g_w2);
    cudaGetSymbolAddress((void**)&bias, g_bias);

    // 0. weight conversion (1 launch) + bias/mask tables
    cvt_all_kernel<<<432, 256>>>(qkv_w, proj_w, fc1_w, fc2_w, wq, wp, w1, w2);
    bias_kernel<<<24, 256>>>(rpb, bias);

    // 1. LN1 + cyclic shift + window partition (bf16 out)
    ln_kernel<true><<<TOK / 8, 256>>>(x, n1g, n1b, xw);
    // 2. QKV projection
    bgemm_kernel<0, bf16><<<dim3(9, TOK / 128), 256>>>(xw, wq, qkv_b, nullptr, qkv, 576, 192);
    // 3. tensor-core windowed attention
    attn_kernel<<<2048 * NHEAD, 128>>>(qkv, bias, att);
    // 4. proj + inverse shift + residual (f32 out)
    bgemm_kernel<1, float><<<dim3(3, TOK / 128), 256>>>(att, wp, proj_b, x, y, 192, 192);
    // 5. LN2 (bf16 out)
    ln_kernel<false><<<TOK / 8, 256>>>(y, n2g, n2b, xn2);
    // 6. FC1 + GELU (bf16 out)
    bgemm_kernel<2, bf16><<<dim3(12, TOK / 128), 256>>>(xn2, w1, fc1_b, nullptr, h1, 768, 192);
    // 7. FC2 + residual -> output (f32)
    bgemm_kernel<3, float><<<dim3(3, TOK / 128), 256>>>(h1, w2, fc2_b, y, out, 192, 768);
}